// round 3
// baseline (speedup 1.0000x reference)
#include <cuda_runtime.h>

#define F_NODES 16384
#define DEG 8
#define E (F_NODES * DEG)   // 131072
#define B 64
#define H 16
#define LAYERS 10
#define CHUNK 32            // batch chunk: per-chunk working set ~69MB fits L2

#define NPB 16              // nodes per block
#define TPN 8               // threads per node (4 batch elems each)
#define NSM 281             // u64 slots per node in smem (280 used + 1 pad for banks)

typedef unsigned long long u64;

// Scratch: x0 transposed (E, B); two (E, CHUNK) ping-pong chunk buffers.
__device__ float g_x0T[(size_t)E * B];
__device__ float g_cA [(size_t)E * CHUNK];
__device__ float g_cB [(size_t)E * CHUNK];

__device__ __forceinline__ u64 pack2(float lo, float hi) {
    u64 r; asm("mov.b64 %0, {%1, %2};" : "=l"(r) : "f"(lo), "f"(hi)); return r;
}
__device__ __forceinline__ void unpack2(u64 v, float& lo, float& hi) {
    asm("mov.b64 {%0, %1}, %2;" : "=f"(lo), "=f"(hi) : "l"(v));
}
__device__ __forceinline__ void fma2(u64& d, u64 a, u64 b, u64 c) {
    asm("fma.rn.f32x2 %0, %1, %2, %3;" : "=l"(d) : "l"(a), "l"(b), "l"(c));
}
// Streaming (evict-first) 16B load: ping-pong src is dead after this layer.
__device__ __forceinline__ float4 ldcs128(const float* p) {
    float4 v;
    asm("ld.global.cs.v4.f32 {%0,%1,%2,%3}, [%4];"
        : "=f"(v.x), "=f"(v.y), "=f"(v.z), "=f"(v.w) : "l"(p));
    return v;
}
// Branchless ELU (alpha=1): max(x,0) + (exp(min(x,0)) - 1)
__device__ __forceinline__ float elu1(float x) {
    return fmaxf(x, 0.0f) + (__expf(fminf(x, 0.0f)) - 1.0f);
}

// (B, E) row-major -> (E, B)
__global__ void k_transpose_in(const float* __restrict__ in, float* __restrict__ out) {
    __shared__ float t[32][33];
    int e0 = blockIdx.x * 32, b0 = blockIdx.y * 32;
    int tx = threadIdx.x, ty = threadIdx.y;
    t[ty][tx] = in[(size_t)(b0 + ty) * E + e0 + tx];
    __syncthreads();
    out[(size_t)(e0 + ty) * B + b0 + tx] = t[tx][ty];
}

// Chunk buffer (E, CHUNK) -> out rows [b_base, b_base+32) of (B, E)
__global__ void k_transpose_out_chunk(const float* __restrict__ in, float* __restrict__ out) {
    __shared__ float t[32][33];
    int e0 = blockIdx.x * 32;
    int tx = threadIdx.x, ty = threadIdx.y;
    t[ty][tx] = in[(size_t)(e0 + ty) * CHUNK + tx];
    __syncthreads();
    out[(size_t)ty * E + e0 + tx] = t[tx][ty];
}

// One GSNN layer for one 32-batch chunk, in transposed (E, chunk) space.
// src: (E, sstride) with this chunk at column offset 0 (pointer pre-offset).
// x0c: x0T pre-offset to this chunk (stride always B=64).
__global__ __launch_bounds__(NPB * TPN)
void layer_kernel(const float* __restrict__ src, int sstride,
                  const float* __restrict__ x0c,
                  float* __restrict__ dst,
                  const float* __restrict__ W1, const float* __restrict__ b1,
                  const float* __restrict__ W2, const float* __restrict__ b2,
                  const int* __restrict__ in_ixs) {
    __shared__ u64 sw[NPB * NSM];
    const int tid  = threadIdx.x;
    const int nl   = tid >> 3;        // node within block
    const int q    = tid & 7;         // batch-quad index: handles b = 4q..4q+3
    const int node = blockIdx.x * NPB + nl;
    u64* w = sw + nl * NSM;

    // Kick off the gather first (longest latency), overlap with weight staging.
    const int4 c0 = ((const int4*)(in_ixs + (size_t)node * 8))[0];
    const int4 c1 = ((const int4*)(in_ixs + (size_t)node * 8))[1];
    const int cols[8] = {c0.x, c0.y, c0.z, c0.w, c1.x, c1.y, c1.z, c1.w};
    float4 g[8];
#pragma unroll
    for (int d = 0; d < 8; d++)
        g[d] = ldcs128(src + (size_t)cols[d] * sstride + (q << 2));

    // Stage weights into smem as duplicated-pair (splat) u64s.
    // Layout per node (u64 index): [0,128) W1 (j*8+d), [128,256) W2 (d*16+j),
    // [256,272) b1, [272,280) b2.
    {
        const float4* gW1 = (const float4*)(W1 + (size_t)node * 128);
        const float4* gW2 = (const float4*)(W2 + (size_t)node * 128);
#pragma unroll
        for (int k = 0; k < 4; k++) {
            float4 a = gW1[q * 4 + k];
            w[q * 16 + k * 4 + 0] = pack2(a.x, a.x);
            w[q * 16 + k * 4 + 1] = pack2(a.y, a.y);
            w[q * 16 + k * 4 + 2] = pack2(a.z, a.z);
            w[q * 16 + k * 4 + 3] = pack2(a.w, a.w);
            float4 b = gW2[q * 4 + k];
            w[128 + q * 16 + k * 4 + 0] = pack2(b.x, b.x);
            w[128 + q * 16 + k * 4 + 1] = pack2(b.y, b.y);
            w[128 + q * 16 + k * 4 + 2] = pack2(b.z, b.z);
            w[128 + q * 16 + k * 4 + 3] = pack2(b.w, b.w);
        }
        float bj0 = b1[(size_t)node * 16 + q * 2];
        float bj1 = b1[(size_t)node * 16 + q * 2 + 1];
        w[256 + q * 2]     = pack2(bj0, bj0);
        w[256 + q * 2 + 1] = pack2(bj1, bj1);
        float bd = b2[(size_t)node * 8 + q];
        w[272 + q] = pack2(bd, bd);
    }
    __syncthreads();

    // View gathered float4s as packed pairs.
    u64 g0[8], g1[8];
#pragma unroll
    for (int d = 0; d < 8; d++) {
        g0[d] = pack2(g[d].x, g[d].y);
        g1[d] = pack2(g[d].z, g[d].w);
    }

    // Output accumulators (8 out dims x 4 batches), init with b2 splats.
    u64 o0[8], o1[8];
#pragma unroll
    for (int d = 0; d < 8; d++) { o0[d] = w[272 + d]; o1[d] = o0[d]; }

    // For each hidden j: h_j = elu(sum_d g_d * W1[j][d] + b1[j]); o_d += h_j*W2[d][j].
#pragma unroll
    for (int j = 0; j < 16; j++) {
        u64 a0 = w[256 + j];
        u64 a1 = a0;
#pragma unroll
        for (int d = 0; d < 8; d++) {
            const u64 wp = w[j * 8 + d];
            fma2(a0, g0[d], wp, a0);
            fma2(a1, g1[d], wp, a1);
        }
        float h0, h1, h2, h3;
        unpack2(a0, h0, h1);
        unpack2(a1, h2, h3);
        h0 = elu1(h0); h1 = elu1(h1); h2 = elu1(h2); h3 = elu1(h3);
        const u64 hh0 = pack2(h0, h1);
        const u64 hh1 = pack2(h2, h3);
#pragma unroll
        for (int d = 0; d < 8; d++) {
            const u64 wp = w[128 + d * 16 + j];
            fma2(o0[d], hh0, wp, o0[d]);
            fma2(o1[d], hh1, wp, o1[d]);
        }
    }

    // Residual from x0 chunk (stride B), store to dst (stride CHUNK).
#pragma unroll
    for (int d = 0; d < 8; d++) {
        const size_t col = (size_t)node * 8 + d;
        const float4 r = *(const float4*)(x0c + col * B + (q << 2));
        float a, b2v, c, dd;
        unpack2(o0[d], a, b2v);
        unpack2(o1[d], c, dd);
        float4 outv = make_float4(a + r.x, b2v + r.y, c + r.z, dd + r.w);
        *(float4*)(dst + col * CHUNK + (q << 2)) = outv;
    }
}

extern "C" void kernel_launch(void* const* d_in, const int* in_sizes, int n_in,
                              void* d_out, int out_size) {
    const float* x0     = (const float*)d_in[0];
    const float* W1     = (const float*)d_in[1];
    const float* b1     = (const float*)d_in[2];
    const float* W2     = (const float*)d_in[3];
    const float* b2     = (const float*)d_in[4];
    const int*   in_ixs = (const int*)d_in[5];
    float* out = (float*)d_out;

    float *x0T, *cA, *cB;
    cudaGetSymbolAddress((void**)&x0T, g_x0T);
    cudaGetSymbolAddress((void**)&cA,  g_cA);
    cudaGetSymbolAddress((void**)&cB,  g_cB);

    k_transpose_in<<<dim3(E / 32, B / 32), dim3(32, 32)>>>(x0, x0T);

    float* bufs[2] = {cA, cB};
    for (int c = 0; c < B / CHUNK; c++) {
        const float* x0c = x0T + CHUNK * c;   // chunk slice of x0T, stride B
        const float* src = x0c;
        int sstride = B;
        for (int L = 0; L < LAYERS; L++) {
            float* dstp = bufs[L & 1];
            layer_kernel<<<F_NODES / NPB, NPB * TPN>>>(src, sstride, x0c, dstp,
                                                       W1, b1, W2, b2, in_ixs);
            src = dstp;
            sstride = CHUNK;
        }
        k_transpose_out_chunk<<<E / 32, dim3(32, 32)>>>(src, out + (size_t)CHUNK * c * E);
    }
}

// round 4
// speedup vs baseline: 1.3371x; 1.3371x over previous
#include <cuda_runtime.h>

#define F_NODES 16384
#define DEG 8
#define E (F_NODES * DEG)   // 131072
#define B 64
#define H 16
#define LAYERS 10

#define NPB 8               // nodes per block
#define TPN 16              // threads per node (4 batch elems each)
#define NSM 281             // u64 slots per node in smem (280 used + 1 pad)

typedef unsigned long long u64;

// Scratch buffers in (E, B) transposed layout.
__device__ float g_x0T[(size_t)E * B];
__device__ float g_xA [(size_t)E * B];
__device__ float g_xB [(size_t)E * B];

__device__ __forceinline__ u64 pack2(float lo, float hi) {
    u64 r; asm("mov.b64 %0, {%1, %2};" : "=l"(r) : "f"(lo), "f"(hi)); return r;
}
__device__ __forceinline__ void unpack2(u64 v, float& lo, float& hi) {
    asm("mov.b64 {%0, %1}, %2;" : "=f"(lo), "=f"(hi) : "l"(v));
}
__device__ __forceinline__ void fma2(u64& d, u64 a, u64 b, u64 c) {
    asm("fma.rn.f32x2 %0, %1, %2, %3;" : "=l"(d) : "l"(a), "l"(b), "l"(c));
}
// Streaming (evict-first) 16B load: ping-pong src is dead after this layer.
// Keeps the dead buffer from evicting x0T/weights out of L2.
__device__ __forceinline__ float4 ldcs128(const float* p) {
    float4 v;
    asm("ld.global.cs.v4.f32 {%0,%1,%2,%3}, [%4];"
        : "=f"(v.x), "=f"(v.y), "=f"(v.z), "=f"(v.w) : "l"(p));
    return v;
}
// Branchless ELU (alpha=1): max(x,0) + (exp(min(x,0)) - 1)
__device__ __forceinline__ float elu1(float x) {
    return fmaxf(x, 0.0f) + (__expf(fminf(x, 0.0f)) - 1.0f);
}

// (B, E) row-major -> (E, B)
__global__ void k_transpose_in(const float* __restrict__ in, float* __restrict__ out) {
    __shared__ float t[32][33];
    int e0 = blockIdx.x * 32, b0 = blockIdx.y * 32;
    int tx = threadIdx.x, ty = threadIdx.y;
    t[ty][tx] = in[(size_t)(b0 + ty) * E + e0 + tx];
    __syncthreads();
    out[(size_t)(e0 + ty) * B + b0 + tx] = t[tx][ty];
}

// (E, B) -> (B, E) row-major
__global__ void k_transpose_out(const float* __restrict__ in, float* __restrict__ out) {
    __shared__ float t[32][33];
    int e0 = blockIdx.x * 32, b0 = blockIdx.y * 32;
    int tx = threadIdx.x, ty = threadIdx.y;
    t[ty][tx] = in[(size_t)(e0 + ty) * B + b0 + tx];
    __syncthreads();
    out[(size_t)(b0 + ty) * E + e0 + tx] = t[tx][ty];
}

// One GSNN layer in (E, B) space. 16 threads/node, 4 batch elems/thread.
__global__ __launch_bounds__(NPB * TPN)
void layer_kernel(const float* __restrict__ src, float* __restrict__ dst,
                  const float* __restrict__ W1, const float* __restrict__ b1,
                  const float* __restrict__ W2, const float* __restrict__ b2,
                  const int* __restrict__ in_ixs, const float* __restrict__ x0T) {
    __shared__ u64 sw[NPB * NSM];
    const int tid  = threadIdx.x;
    const int nl   = tid >> 4;        // node within block
    const int q    = tid & 15;        // batch-quad index: handles b = 4q..4q+3
    const int node = blockIdx.x * NPB + nl;
    u64* w = sw + nl * NSM;

    // Issue the gather first (longest latency), overlap with weight staging.
    const int4 c0 = ((const int4*)(in_ixs + (size_t)node * 8))[0];
    const int4 c1 = ((const int4*)(in_ixs + (size_t)node * 8))[1];
    const int cols[8] = {c0.x, c0.y, c0.z, c0.w, c1.x, c1.y, c1.z, c1.w};
    float4 g[8];
#pragma unroll
    for (int d = 0; d < 8; d++)
        g[d] = ldcs128(src + (((size_t)cols[d]) << 6) + (q << 2));

    // Stage weights into smem as duplicated-pair (splat) u64s.
    // Per-node u64 layout: [0,128) W1 (j*8+d), [128,256) W2 (d*16+j),
    // [256,272) b1, [272,280) b2. 16 threads stage 8 W1 + 8 W2 each.
    {
        const float4* gW1 = (const float4*)(W1 + (size_t)node * 128);
        const float4* gW2 = (const float4*)(W2 + (size_t)node * 128);
#pragma unroll
        for (int k = 0; k < 2; k++) {
            float4 a = gW1[q * 2 + k];
            w[q * 8 + k * 4 + 0] = pack2(a.x, a.x);
            w[q * 8 + k * 4 + 1] = pack2(a.y, a.y);
            w[q * 8 + k * 4 + 2] = pack2(a.z, a.z);
            w[q * 8 + k * 4 + 3] = pack2(a.w, a.w);
            float4 b = gW2[q * 2 + k];
            w[128 + q * 8 + k * 4 + 0] = pack2(b.x, b.x);
            w[128 + q * 8 + k * 4 + 1] = pack2(b.y, b.y);
            w[128 + q * 8 + k * 4 + 2] = pack2(b.z, b.z);
            w[128 + q * 8 + k * 4 + 3] = pack2(b.w, b.w);
        }
        float bj = b1[(size_t)node * 16 + q];
        w[256 + q] = pack2(bj, bj);
        if (q < 8) {
            float bd = b2[(size_t)node * 8 + q];
            w[272 + q] = pack2(bd, bd);
        }
    }
    __syncthreads();

    // View gathered float4s as packed pairs.
    u64 g0[8], g1[8];
#pragma unroll
    for (int d = 0; d < 8; d++) {
        g0[d] = pack2(g[d].x, g[d].y);
        g1[d] = pack2(g[d].z, g[d].w);
    }

    // Output accumulators (8 out dims x 4 batches), init with b2 splats.
    u64 o0[8], o1[8];
#pragma unroll
    for (int d = 0; d < 8; d++) { o0[d] = w[272 + d]; o1[d] = o0[d]; }

    // For each hidden j: h_j = elu(sum_d g_d * W1[j][d] + b1[j]); o_d += h_j*W2[d][j].
#pragma unroll
    for (int j = 0; j < 16; j++) {
        u64 a0 = w[256 + j];
        u64 a1 = a0;
#pragma unroll
        for (int d = 0; d < 8; d++) {
            const u64 wp = w[j * 8 + d];   // LDS.64 broadcast
            fma2(a0, g0[d], wp, a0);
            fma2(a1, g1[d], wp, a1);
        }
        float h0, h1, h2, h3;
        unpack2(a0, h0, h1);
        unpack2(a1, h2, h3);
        h0 = elu1(h0); h1 = elu1(h1); h2 = elu1(h2); h3 = elu1(h3);
        const u64 hh0 = pack2(h0, h1);
        const u64 hh1 = pack2(h2, h3);
#pragma unroll
        for (int d = 0; d < 8; d++) {
            const u64 wp = w[128 + d * 16 + j];
            fma2(o0[d], hh0, wp, o0[d]);
            fma2(o1[d], hh1, wp, o1[d]);
        }
    }

    // Residual from x0T + store; output columns [8*node, 8*node+8) contiguous.
#pragma unroll
    for (int d = 0; d < 8; d++) {
        const size_t col = (size_t)node * 8 + d;
        const float4 r = *(const float4*)(x0T + (col << 6) + (q << 2));
        float a, bb, c, dd;
        unpack2(o0[d], a, bb);
        unpack2(o1[d], c, dd);
        float4 outv = make_float4(a + r.x, bb + r.y, c + r.z, dd + r.w);
        *(float4*)(dst + (col << 6) + (q << 2)) = outv;
    }
}

extern "C" void kernel_launch(void* const* d_in, const int* in_sizes, int n_in,
                              void* d_out, int out_size) {
    const float* x0     = (const float*)d_in[0];
    const float* W1     = (const float*)d_in[1];
    const float* b1     = (const float*)d_in[2];
    const float* W2     = (const float*)d_in[3];
    const float* b2     = (const float*)d_in[4];
    const int*   in_ixs = (const int*)d_in[5];
    float* out = (float*)d_out;

    float *x0T, *xA, *xB;
    cudaGetSymbolAddress((void**)&x0T, g_x0T);
    cudaGetSymbolAddress((void**)&xA,  g_xA);
    cudaGetSymbolAddress((void**)&xB,  g_xB);

    k_transpose_in<<<dim3(E / 32, B / 32), dim3(32, 32)>>>(x0, x0T);

    const float* src = x0T;
    float* bufs[2] = {xA, xB};
    for (int L = 0; L < LAYERS; L++) {
        float* dst = bufs[L & 1];
        layer_kernel<<<F_NODES / NPB, NPB * TPN>>>(src, dst, W1, b1, W2, b2, in_ixs, x0T);
        src = dst;
    }
    k_transpose_out<<<dim3(E / 32, B / 32), dim3(32, 32)>>>(src, out);
}

// round 5
// speedup vs baseline: 1.8257x; 1.3654x over previous
#include <cuda_runtime.h>

#define F_NODES 16384
#define DEG 8
#define E (F_NODES * DEG)   // 131072
#define B 64
#define H 16
#define LAYERS 10

#define NPB 8               // nodes per block
#define TPN 16              // threads per node (4 batch elems each)

typedef unsigned long long u64;

// Scratch buffers in (E, B) transposed layout.
__device__ float g_x0T[(size_t)E * B];
__device__ float g_xA [(size_t)E * B];
__device__ float g_xB [(size_t)E * B];

__device__ __forceinline__ u64 pack2(float lo, float hi) {
    u64 r; asm("mov.b64 %0, {%1, %2};" : "=l"(r) : "f"(lo), "f"(hi)); return r;
}
__device__ __forceinline__ void unpack2(u64 v, float& lo, float& hi) {
    asm("mov.b64 {%0, %1}, %2;" : "=f"(lo), "=f"(hi) : "l"(v));
}
__device__ __forceinline__ void fma2(u64& d, u64 a, u64 b, u64 c) {
    asm("fma.rn.f32x2 %0, %1, %2, %3;" : "=l"(d) : "l"(a), "l"(b), "l"(c));
}
__device__ __forceinline__ u64 add2(u64 a, u64 b) {
    u64 r; asm("add.rn.f32x2 %0, %1, %2;" : "=l"(r) : "l"(a), "l"(b)); return r;
}
// Streaming (evict-first) loads/stores for the dead-after-read ping-pong bufs.
__device__ __forceinline__ float4 ldcs128(const float* p) {
    float4 v;
    asm("ld.global.cs.v4.f32 {%0,%1,%2,%3}, [%4];"
        : "=f"(v.x), "=f"(v.y), "=f"(v.z), "=f"(v.w) : "l"(p));
    return v;
}
__device__ __forceinline__ void stcs128(float* p, float4 v) {
    asm("st.global.cs.v4.f32 [%0], {%1,%2,%3,%4};"
        :: "l"(p), "f"(v.x), "f"(v.y), "f"(v.z), "f"(v.w) : "memory");
}
// Branchless ELU (alpha=1): max(x,0) + (exp(min(x,0)) - 1)
__device__ __forceinline__ float elu1(float x) {
    return fmaxf(x, 0.0f) + (__expf(fminf(x, 0.0f)) - 1.0f);
}

// Per-node smem weights. Stride 1232B: 16B-aligned (LDS.128) and 1232 % 128 = 80
// so the two nodes of a warp hit distinct banks.
struct __align__(16) NodeW {
    u64   sb1[16];     // b1 splats
    u64   sb2[8];      // b2 splats
    float w1[128];     // W1[j][d], j-major (raw global layout)
    float w2t[128];    // W2 transposed: w2t[j*8 + d] = W2[d][j]
    u64   pad[2];
};

// (B, E) row-major -> (E, B)
__global__ void k_transpose_in(const float* __restrict__ in, float* __restrict__ out) {
    __shared__ float t[32][33];
    int e0 = blockIdx.x * 32, b0 = blockIdx.y * 32;
    int tx = threadIdx.x, ty = threadIdx.y;
    t[ty][tx] = in[(size_t)(b0 + ty) * E + e0 + tx];
    __syncthreads();
    out[(size_t)(e0 + ty) * B + b0 + tx] = t[tx][ty];
}

// One GSNN layer in (E, B) space. 16 threads/node, 4 batch elems/thread.
// final==0: dst is (E,B) ping-pong (streaming stores).
// final==1: dst is the (B,E) output; transpose done in registers.
__global__ __launch_bounds__(NPB * TPN)
void layer_kernel(const float* __restrict__ src, float* __restrict__ dst,
                  const float* __restrict__ W1, const float* __restrict__ b1,
                  const float* __restrict__ W2, const float* __restrict__ b2,
                  const int* __restrict__ in_ixs, const float* __restrict__ x0T,
                  int final_flag) {
    __shared__ NodeW sw[NPB];
    const int tid  = threadIdx.x;
    const int nl   = tid >> 4;        // node within block
    const int q    = tid & 15;        // batch-quad: handles b = 4q..4q+3
    const int node = blockIdx.x * NPB + nl;
    NodeW& nw = sw[nl];

    // Issue the gather first (longest latency), overlap with weight staging.
    const int4 c0 = ((const int4*)(in_ixs + (size_t)node * 8))[0];
    const int4 c1 = ((const int4*)(in_ixs + (size_t)node * 8))[1];
    const int cols[8] = {c0.x, c0.y, c0.z, c0.w, c1.x, c1.y, c1.z, c1.w};
    float4 g[8];
#pragma unroll
    for (int d = 0; d < 8; d++)
        g[d] = ldcs128(src + (((size_t)cols[d]) << 6) + (q << 2));

    // Stage weights: W1 raw (float4 copies), W2 transposed (j-major),
    // biases pre-splatted as u64 pairs.
    {
        const float4* gW1 = (const float4*)(W1 + (size_t)node * 128);
        ((float4*)nw.w1)[q * 2]     = gW1[q * 2];
        ((float4*)nw.w1)[q * 2 + 1] = gW1[q * 2 + 1];
        const float* gW2 = W2 + (size_t)node * 128;   // [d][j], d=0..7, j=0..15
#pragma unroll
        for (int d = 0; d < 8; d++)
            nw.w2t[q * 8 + d] = gW2[d * 16 + q];      // w2t[j=q][d]
        float bj = b1[(size_t)node * 16 + q];
        nw.sb1[q] = pack2(bj, bj);
        if (q < 8) {
            float bd = b2[(size_t)node * 8 + q];
            nw.sb2[q] = pack2(bd, bd);
        }
    }
    __syncthreads();

    // Gathered values as packed batch-pairs.
    u64 g0[8], g1[8];
#pragma unroll
    for (int d = 0; d < 8; d++) {
        g0[d] = pack2(g[d].x, g[d].y);
        g1[d] = pack2(g[d].z, g[d].w);
    }

    // Output accumulators (8 out dims x 4 batches), init with b2 splats.
    u64 o0[8], o1[8];
#pragma unroll
    for (int d = 0; d < 8; d++) { o0[d] = nw.sb2[d]; o1[d] = o0[d]; }

#pragma unroll
    for (int j = 0; j < 16; j++) {
        // W1 row j: 8 weights via 2x LDS.128, splat to pairs (ALU movs).
        const float4 wA = ((const float4*)(nw.w1 + j * 8))[0];
        const float4 wB = ((const float4*)(nw.w1 + j * 8))[1];
        u64 s[8];
        s[0] = pack2(wA.x, wA.x); s[1] = pack2(wA.y, wA.y);
        s[2] = pack2(wA.z, wA.z); s[3] = pack2(wA.w, wA.w);
        s[4] = pack2(wB.x, wB.x); s[5] = pack2(wB.y, wB.y);
        s[6] = pack2(wB.z, wB.z); s[7] = pack2(wB.w, wB.w);

        // Two 4-deep chains per batch pair, then combine (shorter critical path).
        u64 pA = nw.sb1[j], pB = 0, pC = pA, pD = 0;
#pragma unroll
        for (int d = 0; d < 4; d++) {
            fma2(pA, g0[d], s[d], pA);
            fma2(pB, g0[d + 4], s[d + 4], pB);
            fma2(pC, g1[d], s[d], pC);
            fma2(pD, g1[d + 4], s[d + 4], pD);
        }
        u64 a0 = add2(pA, pB);
        u64 a1 = add2(pC, pD);

        float h0, h1, h2, h3;
        unpack2(a0, h0, h1);
        unpack2(a1, h2, h3);
        h0 = elu1(h0); h1 = elu1(h1); h2 = elu1(h2); h3 = elu1(h3);
        const u64 hh0 = pack2(h0, h1);
        const u64 hh1 = pack2(h2, h3);

        // W2 column j (transposed in smem): 2x LDS.128 + splats.
        const float4 vA = ((const float4*)(nw.w2t + j * 8))[0];
        const float4 vB = ((const float4*)(nw.w2t + j * 8))[1];
        u64 t[8];
        t[0] = pack2(vA.x, vA.x); t[1] = pack2(vA.y, vA.y);
        t[2] = pack2(vA.z, vA.z); t[3] = pack2(vA.w, vA.w);
        t[4] = pack2(vB.x, vB.x); t[5] = pack2(vB.y, vB.y);
        t[6] = pack2(vB.z, vB.z); t[7] = pack2(vB.w, vB.w);
#pragma unroll
        for (int d = 0; d < 8; d++) {
            fma2(o0[d], hh0, t[d], o0[d]);
            fma2(o1[d], hh1, t[d], o1[d]);
        }
    }

    if (!final_flag) {
        // Residual + streaming store to (E,B) ping-pong.
#pragma unroll
        for (int d = 0; d < 8; d++) {
            const size_t col = (size_t)node * 8 + d;
            const float4 r = *(const float4*)(x0T + (col << 6) + (q << 2));
            float a, bb, c, dd;
            unpack2(o0[d], a, bb);
            unpack2(o1[d], c, dd);
            stcs128(dst + (col << 6) + (q << 2),
                    make_float4(a + r.x, bb + r.y, c + r.z, dd + r.w));
        }
    } else {
        // Residual + register transpose + direct (B,E) output store.
        float ob[4][8];
#pragma unroll
        for (int d = 0; d < 8; d++) {
            const size_t col = (size_t)node * 8 + d;
            const float4 r = *(const float4*)(x0T + (col << 6) + (q << 2));
            float a, bb, c, dd;
            unpack2(o0[d], a, bb);
            unpack2(o1[d], c, dd);
            ob[0][d] = a + r.x; ob[1][d] = bb + r.y;
            ob[2][d] = c + r.z; ob[3][d] = dd + r.w;
        }
#pragma unroll
        for (int rr = 0; rr < 4; rr++) {
            float* p = dst + (size_t)(q * 4 + rr) * E + (size_t)node * 8;
            *(float4*)(p)     = make_float4(ob[rr][0], ob[rr][1], ob[rr][2], ob[rr][3]);
            *(float4*)(p + 4) = make_float4(ob[rr][4], ob[rr][5], ob[rr][6], ob[rr][7]);
        }
    }
}

extern "C" void kernel_launch(void* const* d_in, const int* in_sizes, int n_in,
                              void* d_out, int out_size) {
    const float* x0     = (const float*)d_in[0];
    const float* W1     = (const float*)d_in[1];
    const float* b1     = (const float*)d_in[2];
    const float* W2     = (const float*)d_in[3];
    const float* b2     = (const float*)d_in[4];
    const int*   in_ixs = (const int*)d_in[5];
    float* out = (float*)d_out;

    float *x0T, *xA, *xB;
    cudaGetSymbolAddress((void**)&x0T, g_x0T);
    cudaGetSymbolAddress((void**)&xA,  g_xA);
    cudaGetSymbolAddress((void**)&xB,  g_xB);

    k_transpose_in<<<dim3(E / 32, B / 32), dim3(32, 32)>>>(x0, x0T);

    const float* src = x0T;
    float* bufs[2] = {xA, xB};
    for (int L = 0; L < LAYERS; L++) {
        const int fin = (L == LAYERS - 1);
        float* dst = fin ? out : bufs[L & 1];
        layer_kernel<<<F_NODES / NPB, NPB * TPN>>>(src, dst, W1, b1, W2, b2,
                                                   in_ixs, x0T, fin);
        src = dst;
    }
}